// round 11
// baseline (speedup 1.0000x reference)
#include <cuda_runtime.h>
#include <cuda_fp16.h>
#include <cstdint>

#define N_NODES 100000
#define N_EDGES 1600000
#define F0 128
#define F1 48
#define F2 32
#define SCAN_B 1024
#define SCAN_ITEMS 4
#define SCAN_TILE (SCAN_B * SCAN_ITEMS)
#define N_SCAN_BLK ((N_NODES + SCAN_TILE - 1) / SCAN_TILE)   // 25

typedef unsigned long long u64;

// ---------------- scratch (static device globals; no allocation) ----------------
__device__ int    g_flag32;
__device__ __align__(16) int    g_deg[N_NODES];
__device__ int    g_bflag[N_SCAN_BLK];
__device__ __align__(16) int    g_rowstart[N_NODES];
__device__ __align__(16) int    g_cursor[N_NODES];
__device__ __align__(16) float  g_dis[N_NODES];
__device__ __align__(16) int2   g_epair[N_EDGES];                  // converted (src,dst)
__device__ __align__(16) int    g_esrc[N_EDGES];                   // CSR-ordered src
__device__ __align__(16) __half g_h1h[(size_t)N_NODES * F1];       // dis * (x@W1), fp16
__device__ __align__(16) __half g_h2h[(size_t)N_NODES * F2];       // dis * h2, fp16

__device__ __forceinline__ float4 h4_to_f4(uint2 u) {
    float2 a = __half22float2(*(__half2*)&u.x);
    float2 b = __half22float2(*(__half2*)&u.y);
    return make_float4(a.x, a.y, b.x, b.y);
}

// pair-sum two uint2 (4+4 halves) in fp16, then accumulate into float4
__device__ __forceinline__ void acc_pair(float4& acc, uint2 a, uint2 b) {
    __half2 sx = __hadd2(*(__half2*)&a.x, *(__half2*)&b.x);
    __half2 sy = __hadd2(*(__half2*)&a.y, *(__half2*)&b.y);
    float2 fx = __half22float2(sx);
    float2 fy = __half22float2(sy);
    acc.x += fx.x; acc.y += fx.y; acc.z += fy.x; acc.w += fy.y;
}

__device__ __forceinline__ void acc_one(float4& acc, uint2 a) {
    float4 v = h4_to_f4(a);
    acc.x += v.x; acc.y += v.y; acc.z += v.z; acc.w += v.w;
}

__device__ __forceinline__ unsigned f2tf32(float f) {
    unsigned u;
    asm("cvt.rna.tf32.f32 %0, %1;" : "=r"(u) : "f"(f));
    return u;
}

__device__ __forceinline__ void mma_tf32(float* d, const unsigned* a, const unsigned* b) {
    asm volatile(
        "mma.sync.aligned.m16n8k8.row.col.f32.tf32.tf32.f32 "
        "{%0,%1,%2,%3}, {%4,%5,%6,%7}, {%8,%9}, {%0,%1,%2,%3};\n"
        : "+f"(d[0]), "+f"(d[1]), "+f"(d[2]), "+f"(d[3])
        : "r"(a[0]), "r"(a[1]), "r"(a[2]), "r"(a[3]), "r"(b[0]), "r"(b[1]));
}

// ---------------- init: zero deg + flags, dtype detect ----------------
__global__ void init_kernel(const void* ei) {
    int i = blockIdx.x * blockDim.x + threadIdx.x;
    if (i < N_NODES) g_deg[i] = 0;
    if (i < N_SCAN_BLK) g_bflag[i] = 0;
    if (i == 0) {
        const long long* p = (const long long*)ei;
        int is32 = 0;
        for (int k = 0; k < 256; k++) {
            unsigned long long v = (unsigned long long)p[k];
            if (v >= (unsigned long long)N_NODES) { is32 = 1; break; }
        }
        g_flag32 = is32;
    }
}

// ---------------- convert edge_index -> int32 pairs + degree histogram ----------------
__global__ void convert_count_kernel(const void* ei) {
    int t = blockIdx.x * blockDim.x + threadIdx.x;
    int e = t * 4;
    if (e >= N_EDGES) return;
    int s0, s1, s2, s3, d0, d1, d2, d3;
    if (g_flag32) {
        const int* p = (const int*)ei;
        int4 ss = *(const int4*)(p + e);
        int4 dd = *(const int4*)(p + N_EDGES + e);
        s0 = ss.x; s1 = ss.y; s2 = ss.z; s3 = ss.w;
        d0 = dd.x; d1 = dd.y; d2 = dd.z; d3 = dd.w;
    } else {
        const long long* p = (const long long*)ei;
        longlong2 sa = *(const longlong2*)(p + e);
        longlong2 sb = *(const longlong2*)(p + e + 2);
        longlong2 da = *(const longlong2*)(p + N_EDGES + e);
        longlong2 db = *(const longlong2*)(p + N_EDGES + e + 2);
        s0 = (int)sa.x; s1 = (int)sa.y; s2 = (int)sb.x; s3 = (int)sb.y;
        d0 = (int)da.x; d1 = (int)da.y; d2 = (int)db.x; d3 = (int)db.y;
    }
    *(int4*)&g_epair[e]     = make_int4(s0, d0, s1, d1);
    *(int4*)&g_epair[e + 2] = make_int4(s2, d2, s3, d3);
    atomicAdd(&g_deg[d0], 1);
    atomicAdd(&g_deg[d1], 1);
    atomicAdd(&g_deg[d2], 1);
    atomicAdd(&g_deg[d3], 1);
}

// ---------------- fused scan (4 items/thread): rowstart/cursor/dis ----------------
__global__ __launch_bounds__(SCAN_B) void scan_kernel() {
    __shared__ int wsum[32];
    __shared__ int s_ex;
    int t = threadIdx.x, b = blockIdx.x;
    int i0 = (b * SCAN_B + t) * SCAN_ITEMS;
    int lane = t & 31, wid = t >> 5;

    int4 d4 = make_int4(0, 0, 0, 0);
    if (i0 < N_NODES) d4 = *(const int4*)&g_deg[i0];   // N_NODES % 4 == 0
    int mysum = d4.x + d4.y + d4.z + d4.w;

    int v = mysum;
#pragma unroll
    for (int o = 1; o < 32; o <<= 1) {
        int n = __shfl_up_sync(0xffffffffu, v, o);
        if (lane >= o) v += n;
    }
    if (lane == 31) wsum[wid] = v;
    __syncthreads();

    if (wid == 0) {
        int w = wsum[lane];
        int wv = w;
#pragma unroll
        for (int o = 1; o < 32; o <<= 1) {
            int n = __shfl_up_sync(0xffffffffu, wv, o);
            if (lane >= o) wv += n;
        }
        wsum[lane] = wv - w;
        if (lane == 31)
            *(volatile int*)&g_bflag[b] = wv + 1;
    }
    __syncthreads();

    if (t < 32) {
        int sum = 0;
        for (int j = t; j < b; j += 32) {
            int vv;
            while ((vv = *(volatile int*)&g_bflag[j]) == 0) { }
            sum += vv - 1;
        }
#pragma unroll
        for (int o = 16; o; o >>= 1) sum += __shfl_down_sync(0xffffffffu, sum, o);
        if (t == 0) s_ex = sum;
    }
    __syncthreads();

    if (i0 < N_NODES) {
        int ex = s_ex + wsum[wid] + (v - mysum);
        int4 rs;
        rs.x = ex;
        rs.y = ex + d4.x;
        rs.z = rs.y + d4.y;
        rs.w = rs.z + d4.z;
        *(int4*)&g_rowstart[i0] = rs;
        *(int4*)&g_cursor[i0] = rs;
        float4 dis;
        dis.x = rsqrtf((float)(d4.x + 1));
        dis.y = rsqrtf((float)(d4.y + 1));
        dis.z = rsqrtf((float)(d4.z + 1));
        dis.w = rsqrtf((float)(d4.w + 1));
        *(float4*)&g_dis[i0] = dis;
    }
}

// ---------------- bucket edges into CSR order (reads compact int2 pairs) ----------------
__global__ void csr_scatter_kernel() {
    int t = blockIdx.x * blockDim.x + threadIdx.x;
    int e = t * 2;
    if (e >= N_EDGES) return;
    int4 p = *(const int4*)&g_epair[e];    // (s0,d0,s1,d1)
    g_esrc[atomicAdd(&g_cursor[p.y], 1)] = p.x;
    g_esrc[atomicAdd(&g_cursor[p.w], 1)] = p.z;
}

// ---------------- GEMM1 on tensor cores: h1u = x @ W1 -> fp16 UNSCALED ----------------
__global__ __launch_bounds__(256) void gemm1_kernel(const float* __restrict__ x,
                                                    const float* __restrict__ W1) {
    __shared__ unsigned wst[48][132];

    int tid = threadIdx.x;
    for (int idx = tid; idx < F0 * F1; idx += 256) {
        int k = idx / F1, c = idx % F1;
        wst[c][k] = f2tf32(W1[idx]);
    }
    __syncthreads();

    int w = tid >> 5, lane = tid & 31;
    int gid = lane >> 2, tig = lane & 3;
    int rbase = blockIdx.x * 256 + w * 32;

    float d[2][6][4];
#pragma unroll
    for (int mi = 0; mi < 2; mi++)
#pragma unroll
        for (int ni = 0; ni < 6; ni++)
#pragma unroll
            for (int q = 0; q < 4; q++) d[mi][ni][q] = 0.0f;

    int r0[2], r1[2];
    bool v0[2], v1[2];
#pragma unroll
    for (int mi = 0; mi < 2; mi++) {
        r0[mi] = rbase + mi * 16 + gid;
        r1[mi] = r0[mi] + 8;
        v0[mi] = r0[mi] < N_NODES;
        v1[mi] = r1[mi] < N_NODES;
    }

#pragma unroll
    for (int k0 = 0; k0 < F0; k0 += 8) {
        unsigned a[2][4];
#pragma unroll
        for (int mi = 0; mi < 2; mi++) {
            const float* p0 = x + (size_t)r0[mi] * F0 + k0 + tig;
            const float* p1 = x + (size_t)r1[mi] * F0 + k0 + tig;
            float f0 = v0[mi] ? __ldg(p0) : 0.0f;
            float f1 = v1[mi] ? __ldg(p1) : 0.0f;
            float f2 = v0[mi] ? __ldg(p0 + 4) : 0.0f;
            float f3 = v1[mi] ? __ldg(p1 + 4) : 0.0f;
            a[mi][0] = f2tf32(f0);
            a[mi][1] = f2tf32(f1);
            a[mi][2] = f2tf32(f2);
            a[mi][3] = f2tf32(f3);
        }
        unsigned b[6][2];
#pragma unroll
        for (int ni = 0; ni < 6; ni++) {
            b[ni][0] = wst[ni * 8 + gid][k0 + tig];
            b[ni][1] = wst[ni * 8 + gid][k0 + tig + 4];
        }
#pragma unroll
        for (int mi = 0; mi < 2; mi++)
#pragma unroll
            for (int ni = 0; ni < 6; ni++)
                mma_tf32(d[mi][ni], a[mi], b[ni]);
    }

#pragma unroll
    for (int mi = 0; mi < 2; mi++) {
#pragma unroll
        for (int ni = 0; ni < 6; ni++) {
            int col = ni * 8 + tig * 2;
            if (v0[mi])
                *(__half2*)(g_h1h + (size_t)r0[mi] * F1 + col) =
                    __floats2half2_rn(d[mi][ni][0], d[mi][ni][1]);
            if (v1[mi])
                *(__half2*)(g_h1h + (size_t)r1[mi] * F1 + col) =
                    __floats2half2_rn(d[mi][ni][2], d[mi][ni][3]);
        }
    }
}

// ---------------- scale h1 by dis (after scan; streaming) ----------------
__global__ void scale_h1_kernel() {
    int idx = blockIdx.x * blockDim.x + threadIdx.x;
    if (idx >= N_NODES * 6) return;
    int row = idx / 6;
    float d = g_dis[row];
    uint4* p = (uint4*)(g_h1h + (size_t)idx * 8);
    uint4 u = *p;
    float2 f0 = __half22float2(*(__half2*)&u.x);
    float2 f1 = __half22float2(*(__half2*)&u.y);
    float2 f2 = __half22float2(*(__half2*)&u.z);
    float2 f3 = __half22float2(*(__half2*)&u.w);
    __half2 h0 = __floats2half2_rn(f0.x * d, f0.y * d);
    __half2 h1 = __floats2half2_rn(f1.x * d, f1.y * d);
    __half2 h2 = __floats2half2_rn(f2.x * d, f2.y * d);
    __half2 h3 = __floats2half2_rn(f3.x * d, f3.y * d);
    u.x = *(unsigned*)&h0;
    u.y = *(unsigned*)&h1;
    u.z = *(unsigned*)&h2;
    u.w = *(unsigned*)&h3;
    *p = u;
}

// ---------------- layer-1 gather + bias/relu + block-GEMM2 -> h2s (fp16) ----------------
#define A1_NODES 64
__global__ __launch_bounds__(256) void agg1_mid_kernel(const float* __restrict__ b1,
                                                       const float* __restrict__ W2) {
    __shared__ __align__(16) float zs[A1_NODES][52];
    __shared__ __align__(16) float ws2t[48][36];       // W2 [k][c], padded

    int tid = threadIdx.x;
    for (int idx = tid; idx < F1 * F2; idx += 256) {
        int k = idx >> 5, c = idx & 31;
        ws2t[k][c] = W2[idx];
    }

    int w = tid >> 5, lane = tid & 31;
    int base = blockIdx.x * A1_NODES;
    bool active = lane < 24;
    int grp = lane / 12;
    int sl  = lane % 12;

    float4 b1v = make_float4(0.f, 0.f, 0.f, 0.f);
    if (active) b1v = ((const float4*)b1)[sl];

    for (int i = 0; i < 4; i++) {
        int r = w * 8 + i * 2 + grp;
        int node = base + r;
        if (active) {
            if (node < N_NODES) {
                float drow = g_dis[node];
                const __half* hrow = g_h1h + (size_t)node * F1 + sl * 4;
                float4 acc = h4_to_f4(*(const uint2*)hrow);   // self: dis*h1s

                int rs = g_rowstart[node];
                int re = rs + g_deg[node];
                int e = rs;
                // align e to 4 (<=3 scalar edges)
                for (; e < re && (e & 3); e++)
                    acc_one(acc, *(const uint2*)(g_h1h + (size_t)g_esrc[e] * F1 + sl * 4));
                // 16-edge batches: 4x int4 idx loads, fp16 pair-sums
                for (; e + 16 <= re; e += 16) {
                    int4 s4[4]; uint2 u[16];
#pragma unroll
                    for (int m = 0; m < 4; m++) s4[m] = *(const int4*)&g_esrc[e + 4 * m];
                    const int* sp = (const int*)s4;
#pragma unroll
                    for (int q = 0; q < 16; q++)
                        u[q] = *(const uint2*)(g_h1h + (size_t)sp[q] * F1 + sl * 4);
#pragma unroll
                    for (int q = 0; q < 8; q++)
                        acc_pair(acc, u[2 * q], u[2 * q + 1]);
                }
                if (e + 8 <= re) {
                    int4 s4[2]; uint2 u[8];
#pragma unroll
                    for (int m = 0; m < 2; m++) s4[m] = *(const int4*)&g_esrc[e + 4 * m];
                    const int* sp = (const int*)s4;
#pragma unroll
                    for (int q = 0; q < 8; q++)
                        u[q] = *(const uint2*)(g_h1h + (size_t)sp[q] * F1 + sl * 4);
#pragma unroll
                    for (int q = 0; q < 4; q++)
                        acc_pair(acc, u[2 * q], u[2 * q + 1]);
                    e += 8;
                }
                if (e + 4 <= re) {
                    int4 s4 = *(const int4*)&g_esrc[e];
                    uint2 u[4];
                    u[0] = *(const uint2*)(g_h1h + (size_t)s4.x * F1 + sl * 4);
                    u[1] = *(const uint2*)(g_h1h + (size_t)s4.y * F1 + sl * 4);
                    u[2] = *(const uint2*)(g_h1h + (size_t)s4.z * F1 + sl * 4);
                    u[3] = *(const uint2*)(g_h1h + (size_t)s4.w * F1 + sl * 4);
                    acc_pair(acc, u[0], u[1]);
                    acc_pair(acc, u[2], u[3]);
                    e += 4;
                }
                for (; e < re; e++)
                    acc_one(acc, *(const uint2*)(g_h1h + (size_t)g_esrc[e] * F1 + sl * 4));

                float4 z;
                z.x = fmaxf(fmaf(drow, acc.x, b1v.x), 0.0f);
                z.y = fmaxf(fmaf(drow, acc.y, b1v.y), 0.0f);
                z.z = fmaxf(fmaf(drow, acc.z, b1v.z), 0.0f);
                z.w = fmaxf(fmaf(drow, acc.w, b1v.w), 0.0f);
                *(float4*)&zs[r][sl * 4] = z;
            } else {
                *(float4*)&zs[r][sl * 4] = make_float4(0.f, 0.f, 0.f, 0.f);
            }
        }
    }
    __syncthreads();

    int ng = tid >> 3;
    int cg = tid & 7;
    int r0 = ng * 2;
    int c0 = cg * 4;

    float acc[2][4];
#pragma unroll
    for (int i = 0; i < 2; i++)
#pragma unroll
        for (int j = 0; j < 4; j++) acc[i][j] = 0.0f;

#pragma unroll 4
    for (int k = 0; k < F1; k++) {
        float4 wv = *(const float4*)&ws2t[k][c0];
        float z0 = zs[r0 + 0][k];
        float z1 = zs[r0 + 1][k];
        acc[0][0] += z0 * wv.x; acc[0][1] += z0 * wv.y; acc[0][2] += z0 * wv.z; acc[0][3] += z0 * wv.w;
        acc[1][0] += z1 * wv.x; acc[1][1] += z1 * wv.y; acc[1][2] += z1 * wv.z; acc[1][3] += z1 * wv.w;
    }

#pragma unroll
    for (int i = 0; i < 2; i++) {
        int node = base + r0 + i;
        if (node < N_NODES) {
            float d = g_dis[node];
            __half2 p0 = __floats2half2_rn(acc[i][0] * d, acc[i][1] * d);
            __half2 p1 = __floats2half2_rn(acc[i][2] * d, acc[i][3] * d);
            uint2 pk;
            pk.x = *(unsigned*)&p0;
            pk.y = *(unsigned*)&p1;
            *(uint2*)(g_h2h + (size_t)node * F2 + c0) = pk;
        }
    }
}

// ---------------- layer-2 gather + bias -> out ----------------
#define A2_BLOCKS 592
__global__ __launch_bounds__(512) void agg2_kernel(const float* __restrict__ b2,
                                                   float* __restrict__ out) {
    int tid = threadIdx.x;
    int w = tid >> 5, lane = tid & 31;
    int grp = lane >> 3, sl = lane & 7;
    int quad0 = blockIdx.x * 16 + w;
    int n_quads = gridDim.x * 16;
    float4 b2v = ((const float4*)b2)[sl];

    for (int p = quad0; p * 4 + grp < N_NODES; p += n_quads) {
        int row = p * 4 + grp;
        float drow = g_dis[row];
        float4 acc = h4_to_f4(((const uint2*)(g_h2h + (size_t)row * F2))[sl]);

        int rs = g_rowstart[row];
        int re = rs + g_deg[row];
        int e = rs;
        for (; e < re && (e & 3); e++)
            acc_one(acc, ((const uint2*)(g_h2h + (size_t)g_esrc[e] * F2))[sl]);
        for (; e + 16 <= re; e += 16) {
            int4 s4[4]; uint2 u[16];
#pragma unroll
            for (int m = 0; m < 4; m++) s4[m] = *(const int4*)&g_esrc[e + 4 * m];
            const int* sp = (const int*)s4;
#pragma unroll
            for (int q = 0; q < 16; q++)
                u[q] = ((const uint2*)(g_h2h + (size_t)sp[q] * F2))[sl];
#pragma unroll
            for (int q = 0; q < 8; q++)
                acc_pair(acc, u[2 * q], u[2 * q + 1]);
        }
        if (e + 8 <= re) {
            int4 s4[2]; uint2 u[8];
#pragma unroll
            for (int m = 0; m < 2; m++) s4[m] = *(const int4*)&g_esrc[e + 4 * m];
            const int* sp = (const int*)s4;
#pragma unroll
            for (int q = 0; q < 8; q++)
                u[q] = ((const uint2*)(g_h2h + (size_t)sp[q] * F2))[sl];
#pragma unroll
            for (int q = 0; q < 4; q++)
                acc_pair(acc, u[2 * q], u[2 * q + 1]);
            e += 8;
        }
        if (e + 4 <= re) {
            int4 s4 = *(const int4*)&g_esrc[e];
            uint2 u[4];
            u[0] = ((const uint2*)(g_h2h + (size_t)s4.x * F2))[sl];
            u[1] = ((const uint2*)(g_h2h + (size_t)s4.y * F2))[sl];
            u[2] = ((const uint2*)(g_h2h + (size_t)s4.z * F2))[sl];
            u[3] = ((const uint2*)(g_h2h + (size_t)s4.w * F2))[sl];
            acc_pair(acc, u[0], u[1]);
            acc_pair(acc, u[2], u[3]);
            e += 4;
        }
        for (; e < re; e++)
            acc_one(acc, ((const uint2*)(g_h2h + (size_t)g_esrc[e] * F2))[sl]);

        float4 o;
        o.x = fmaf(drow, acc.x, b2v.x);
        o.y = fmaf(drow, acc.y, b2v.y);
        o.z = fmaf(drow, acc.z, b2v.z);
        o.w = fmaf(drow, acc.w, b2v.w);
        ((float4*)(out + (size_t)row * F2))[sl] = o;
    }
}

// ---------------- launch ----------------
extern "C" void kernel_launch(void* const* d_in, const int* in_sizes, int n_in,
                              void* d_out, int out_size) {
    const float* x  = (const float*)d_in[0];
    const void*  ei = d_in[1];
    const float* W1 = (const float*)d_in[2];
    const float* b1 = (const float*)d_in[3];
    const float* W2 = (const float*)d_in[4];
    const float* b2 = (const float*)d_in[5];
    float* out = (float*)d_out;

    cudaStream_t s2;
    cudaStreamCreateWithFlags(&s2, cudaStreamNonBlocking);
    cudaEvent_t evRoot, evScan, evG;
    cudaEventCreateWithFlags(&evRoot, cudaEventDisableTiming);
    cudaEventCreateWithFlags(&evScan, cudaEventDisableTiming);
    cudaEventCreateWithFlags(&evG, cudaEventDisableTiming);

    // fork at t=0: tensor-core gemm1 (unscaled) depends only on x/W1
    cudaEventRecord(evRoot, 0);
    cudaStreamWaitEvent(s2, evRoot, 0);
    gemm1_kernel<<<(N_NODES + 255) / 256, 256, 0, s2>>>(x, W1);

    // main chain: CSR build
    init_kernel<<<(N_NODES + 255) / 256, 256>>>(ei);
    convert_count_kernel<<<(N_EDGES / 4 + 255) / 256, 256>>>(ei);
    scan_kernel<<<N_SCAN_BLK, SCAN_B>>>();
    cudaEventRecord(evScan, 0);

    // side stream: scale h1 by dis (needs gemm1 done + scan done)
    cudaStreamWaitEvent(s2, evScan, 0);
    scale_h1_kernel<<<(N_NODES * 6 + 255) / 256, 256, 0, s2>>>();
    cudaEventRecord(evG, s2);

    csr_scatter_kernel<<<(N_EDGES / 2 + 255) / 256, 256>>>();

    // join, then the two gather stages
    cudaStreamWaitEvent(0, evG, 0);
    agg1_mid_kernel<<<(N_NODES + A1_NODES - 1) / A1_NODES, 256>>>(b1, W2);
    agg2_kernel<<<A2_BLOCKS, 512>>>(b2, out);
}

// round 12
// speedup vs baseline: 1.0908x; 1.0908x over previous
#include <cuda_runtime.h>
#include <cuda_fp16.h>
#include <cstdint>

#define N_NODES 100000
#define N_EDGES 1600000
#define F0 128
#define F1 48
#define F2 32
#define SCAN_B 1024
#define SCAN_ITEMS 4
#define SCAN_TILE (SCAN_B * SCAN_ITEMS)
#define N_SCAN_BLK ((N_NODES + SCAN_TILE - 1) / SCAN_TILE)   // 25

typedef unsigned long long u64;

// ---------------- scratch (static device globals; no allocation) ----------------
__device__ int    g_flag32;
__device__ __align__(16) int    g_deg[N_NODES];
__device__ int    g_bflag[N_SCAN_BLK];
__device__ __align__(16) int    g_rowstart[N_NODES];
__device__ __align__(16) int    g_cursor[N_NODES];
__device__ __align__(16) float  g_dis[N_NODES];
__device__ __align__(16) int2   g_epair[N_EDGES];                  // converted (src,dst)
__device__ __align__(16) int    g_esrc[N_EDGES];                   // CSR-ordered src
__device__ __align__(16) __half g_h1h[(size_t)N_NODES * F1];       // dis * (x@W1), fp16
__device__ __align__(16) __half g_h2h[(size_t)N_NODES * F2];       // dis * h2, fp16

__device__ __forceinline__ float4 h4_to_f4(uint2 u) {
    float2 a = __half22float2(*(__half2*)&u.x);
    float2 b = __half22float2(*(__half2*)&u.y);
    return make_float4(a.x, a.y, b.x, b.y);
}

// pair-sum two uint2 (4+4 halves) in fp16, then accumulate into float4
__device__ __forceinline__ void acc_pair(float4& acc, uint2 a, uint2 b) {
    __half2 sx = __hadd2(*(__half2*)&a.x, *(__half2*)&b.x);
    __half2 sy = __hadd2(*(__half2*)&a.y, *(__half2*)&b.y);
    float2 fx = __half22float2(sx);
    float2 fy = __half22float2(sy);
    acc.x += fx.x; acc.y += fx.y; acc.z += fy.x; acc.w += fy.y;
}

__device__ __forceinline__ void acc_one(float4& acc, uint2 a) {
    float4 v = h4_to_f4(a);
    acc.x += v.x; acc.y += v.y; acc.z += v.z; acc.w += v.w;
}

__device__ __forceinline__ unsigned f2tf32(float f) {
    unsigned u;
    asm("cvt.rna.tf32.f32 %0, %1;" : "=r"(u) : "f"(f));
    return u;
}

__device__ __forceinline__ void mma_tf32(float* d, const unsigned* a, const unsigned* b) {
    asm volatile(
        "mma.sync.aligned.m16n8k8.row.col.f32.tf32.tf32.f32 "
        "{%0,%1,%2,%3}, {%4,%5,%6,%7}, {%8,%9}, {%0,%1,%2,%3};\n"
        : "+f"(d[0]), "+f"(d[1]), "+f"(d[2]), "+f"(d[3])
        : "r"(a[0]), "r"(a[1]), "r"(a[2]), "r"(a[3]), "r"(b[0]), "r"(b[1]));
}

// ---------------- init: zero deg + flags, dtype detect ----------------
__global__ void init_kernel(const void* ei) {
    int i = blockIdx.x * blockDim.x + threadIdx.x;
    if (i < N_NODES) g_deg[i] = 0;
    if (i < N_SCAN_BLK) g_bflag[i] = 0;
    if (i == 0) {
        const long long* p = (const long long*)ei;
        int is32 = 0;
        for (int k = 0; k < 256; k++) {
            unsigned long long v = (unsigned long long)p[k];
            if (v >= (unsigned long long)N_NODES) { is32 = 1; break; }
        }
        g_flag32 = is32;
    }
}

// ---------------- convert edge_index -> int32 pairs + degree histogram ----------------
__global__ void convert_count_kernel(const void* ei) {
    int t = blockIdx.x * blockDim.x + threadIdx.x;
    int e = t * 4;
    if (e >= N_EDGES) return;
    int s0, s1, s2, s3, d0, d1, d2, d3;
    if (g_flag32) {
        const int* p = (const int*)ei;
        int4 ss = *(const int4*)(p + e);
        int4 dd = *(const int4*)(p + N_EDGES + e);
        s0 = ss.x; s1 = ss.y; s2 = ss.z; s3 = ss.w;
        d0 = dd.x; d1 = dd.y; d2 = dd.z; d3 = dd.w;
    } else {
        const long long* p = (const long long*)ei;
        longlong2 sa = *(const longlong2*)(p + e);
        longlong2 sb = *(const longlong2*)(p + e + 2);
        longlong2 da = *(const longlong2*)(p + N_EDGES + e);
        longlong2 db = *(const longlong2*)(p + N_EDGES + e + 2);
        s0 = (int)sa.x; s1 = (int)sa.y; s2 = (int)sb.x; s3 = (int)sb.y;
        d0 = (int)da.x; d1 = (int)da.y; d2 = (int)db.x; d3 = (int)db.y;
    }
    *(int4*)&g_epair[e]     = make_int4(s0, d0, s1, d1);
    *(int4*)&g_epair[e + 2] = make_int4(s2, d2, s3, d3);
    atomicAdd(&g_deg[d0], 1);
    atomicAdd(&g_deg[d1], 1);
    atomicAdd(&g_deg[d2], 1);
    atomicAdd(&g_deg[d3], 1);
}

// ---------------- fused scan (4 items/thread): rowstart/cursor/dis ----------------
__global__ __launch_bounds__(SCAN_B) void scan_kernel() {
    __shared__ int wsum[32];
    __shared__ int s_ex;
    int t = threadIdx.x, b = blockIdx.x;
    int i0 = (b * SCAN_B + t) * SCAN_ITEMS;
    int lane = t & 31, wid = t >> 5;

    int4 d4 = make_int4(0, 0, 0, 0);
    if (i0 < N_NODES) d4 = *(const int4*)&g_deg[i0];   // N_NODES % 4 == 0
    int mysum = d4.x + d4.y + d4.z + d4.w;

    int v = mysum;
#pragma unroll
    for (int o = 1; o < 32; o <<= 1) {
        int n = __shfl_up_sync(0xffffffffu, v, o);
        if (lane >= o) v += n;
    }
    if (lane == 31) wsum[wid] = v;
    __syncthreads();

    if (wid == 0) {
        int w = wsum[lane];
        int wv = w;
#pragma unroll
        for (int o = 1; o < 32; o <<= 1) {
            int n = __shfl_up_sync(0xffffffffu, wv, o);
            if (lane >= o) wv += n;
        }
        wsum[lane] = wv - w;
        if (lane == 31)
            *(volatile int*)&g_bflag[b] = wv + 1;
    }
    __syncthreads();

    if (t < 32) {
        int sum = 0;
        for (int j = t; j < b; j += 32) {
            int vv;
            while ((vv = *(volatile int*)&g_bflag[j]) == 0) { }
            sum += vv - 1;
        }
#pragma unroll
        for (int o = 16; o; o >>= 1) sum += __shfl_down_sync(0xffffffffu, sum, o);
        if (t == 0) s_ex = sum;
    }
    __syncthreads();

    if (i0 < N_NODES) {
        int ex = s_ex + wsum[wid] + (v - mysum);
        int4 rs;
        rs.x = ex;
        rs.y = ex + d4.x;
        rs.z = rs.y + d4.y;
        rs.w = rs.z + d4.z;
        *(int4*)&g_rowstart[i0] = rs;
        *(int4*)&g_cursor[i0] = rs;
        float4 dis;
        dis.x = rsqrtf((float)(d4.x + 1));
        dis.y = rsqrtf((float)(d4.y + 1));
        dis.z = rsqrtf((float)(d4.z + 1));
        dis.w = rsqrtf((float)(d4.w + 1));
        *(float4*)&g_dis[i0] = dis;
    }
}

// ---------------- bucket edges into CSR order (reads compact int2 pairs) ----------------
__global__ void csr_scatter_kernel() {
    int t = blockIdx.x * blockDim.x + threadIdx.x;
    int e = t * 2;
    if (e >= N_EDGES) return;
    int4 p = *(const int4*)&g_epair[e];    // (s0,d0,s1,d1)
    g_esrc[atomicAdd(&g_cursor[p.y], 1)] = p.x;
    g_esrc[atomicAdd(&g_cursor[p.w], 1)] = p.z;
}

// ---------------- GEMM1 on tensor cores: h1u = x @ W1 -> fp16 UNSCALED ----------------
__global__ __launch_bounds__(256) void gemm1_kernel(const float* __restrict__ x,
                                                    const float* __restrict__ W1) {
    __shared__ unsigned wst[48][132];

    int tid = threadIdx.x;
    for (int idx = tid; idx < F0 * F1; idx += 256) {
        int k = idx / F1, c = idx % F1;
        wst[c][k] = f2tf32(W1[idx]);
    }
    __syncthreads();

    int w = tid >> 5, lane = tid & 31;
    int gid = lane >> 2, tig = lane & 3;
    int rbase = blockIdx.x * 256 + w * 32;

    float d[2][6][4];
#pragma unroll
    for (int mi = 0; mi < 2; mi++)
#pragma unroll
        for (int ni = 0; ni < 6; ni++)
#pragma unroll
            for (int q = 0; q < 4; q++) d[mi][ni][q] = 0.0f;

    int r0[2], r1[2];
    bool v0[2], v1[2];
#pragma unroll
    for (int mi = 0; mi < 2; mi++) {
        r0[mi] = rbase + mi * 16 + gid;
        r1[mi] = r0[mi] + 8;
        v0[mi] = r0[mi] < N_NODES;
        v1[mi] = r1[mi] < N_NODES;
    }

#pragma unroll
    for (int k0 = 0; k0 < F0; k0 += 8) {
        unsigned a[2][4];
#pragma unroll
        for (int mi = 0; mi < 2; mi++) {
            const float* p0 = x + (size_t)r0[mi] * F0 + k0 + tig;
            const float* p1 = x + (size_t)r1[mi] * F0 + k0 + tig;
            float f0 = v0[mi] ? __ldg(p0) : 0.0f;
            float f1 = v1[mi] ? __ldg(p1) : 0.0f;
            float f2 = v0[mi] ? __ldg(p0 + 4) : 0.0f;
            float f3 = v1[mi] ? __ldg(p1 + 4) : 0.0f;
            a[mi][0] = f2tf32(f0);
            a[mi][1] = f2tf32(f1);
            a[mi][2] = f2tf32(f2);
            a[mi][3] = f2tf32(f3);
        }
        unsigned b[6][2];
#pragma unroll
        for (int ni = 0; ni < 6; ni++) {
            b[ni][0] = wst[ni * 8 + gid][k0 + tig];
            b[ni][1] = wst[ni * 8 + gid][k0 + tig + 4];
        }
#pragma unroll
        for (int mi = 0; mi < 2; mi++)
#pragma unroll
            for (int ni = 0; ni < 6; ni++)
                mma_tf32(d[mi][ni], a[mi], b[ni]);
    }

#pragma unroll
    for (int mi = 0; mi < 2; mi++) {
#pragma unroll
        for (int ni = 0; ni < 6; ni++) {
            int col = ni * 8 + tig * 2;
            if (v0[mi])
                *(__half2*)(g_h1h + (size_t)r0[mi] * F1 + col) =
                    __floats2half2_rn(d[mi][ni][0], d[mi][ni][1]);
            if (v1[mi])
                *(__half2*)(g_h1h + (size_t)r1[mi] * F1 + col) =
                    __floats2half2_rn(d[mi][ni][2], d[mi][ni][3]);
        }
    }
}

// ---------------- scale h1 by dis (after scan; streaming) ----------------
__global__ void scale_h1_kernel() {
    int idx = blockIdx.x * blockDim.x + threadIdx.x;
    if (idx >= N_NODES * 6) return;
    int row = idx / 6;
    float d = g_dis[row];
    uint4* p = (uint4*)(g_h1h + (size_t)idx * 8);
    uint4 u = *p;
    float2 f0 = __half22float2(*(__half2*)&u.x);
    float2 f1 = __half22float2(*(__half2*)&u.y);
    float2 f2 = __half22float2(*(__half2*)&u.z);
    float2 f3 = __half22float2(*(__half2*)&u.w);
    __half2 h0 = __floats2half2_rn(f0.x * d, f0.y * d);
    __half2 h1 = __floats2half2_rn(f1.x * d, f1.y * d);
    __half2 h2 = __floats2half2_rn(f2.x * d, f2.y * d);
    __half2 h3 = __floats2half2_rn(f3.x * d, f3.y * d);
    u.x = *(unsigned*)&h0;
    u.y = *(unsigned*)&h1;
    u.z = *(unsigned*)&h2;
    u.w = *(unsigned*)&h3;
    *p = u;
}

// ---------------- layer-1 gather + bias/relu + block-GEMM2 -> h2s (fp16) ----------------
// R10 batch structure (16/8/4/scalar from rs, scalar idx loads) + fp16 pair-sums.
#define A1_NODES 64
__global__ __launch_bounds__(256) void agg1_mid_kernel(const float* __restrict__ b1,
                                                       const float* __restrict__ W2) {
    __shared__ __align__(16) float zs[A1_NODES][52];
    __shared__ __align__(16) float ws2t[48][36];       // W2 [k][c], padded

    int tid = threadIdx.x;
    for (int idx = tid; idx < F1 * F2; idx += 256) {
        int k = idx >> 5, c = idx & 31;
        ws2t[k][c] = W2[idx];
    }

    int w = tid >> 5, lane = tid & 31;
    int base = blockIdx.x * A1_NODES;
    bool active = lane < 24;
    int grp = lane / 12;
    int sl  = lane % 12;

    float4 b1v = make_float4(0.f, 0.f, 0.f, 0.f);
    if (active) b1v = ((const float4*)b1)[sl];

    for (int i = 0; i < 4; i++) {
        int r = w * 8 + i * 2 + grp;
        int node = base + r;
        if (active) {
            if (node < N_NODES) {
                float drow = g_dis[node];
                const __half* hrow = g_h1h + (size_t)node * F1 + sl * 4;
                float4 acc = h4_to_f4(*(const uint2*)hrow);   // self: dis*h1s

                int rs = g_rowstart[node];
                int re = rs + g_deg[node];
                int e = rs;
                for (; e + 16 <= re; e += 16) {
                    int s[16]; uint2 u[16];
#pragma unroll
                    for (int q = 0; q < 16; q++) s[q] = g_esrc[e + q];
#pragma unroll
                    for (int q = 0; q < 16; q++)
                        u[q] = *(const uint2*)(g_h1h + (size_t)s[q] * F1 + sl * 4);
#pragma unroll
                    for (int q = 0; q < 8; q++)
                        acc_pair(acc, u[2 * q], u[2 * q + 1]);
                }
                if (e + 8 <= re) {
                    int s[8]; uint2 u[8];
#pragma unroll
                    for (int q = 0; q < 8; q++) s[q] = g_esrc[e + q];
#pragma unroll
                    for (int q = 0; q < 8; q++)
                        u[q] = *(const uint2*)(g_h1h + (size_t)s[q] * F1 + sl * 4);
#pragma unroll
                    for (int q = 0; q < 4; q++)
                        acc_pair(acc, u[2 * q], u[2 * q + 1]);
                    e += 8;
                }
                if (e + 4 <= re) {
                    int s[4]; uint2 u[4];
#pragma unroll
                    for (int q = 0; q < 4; q++) s[q] = g_esrc[e + q];
#pragma unroll
                    for (int q = 0; q < 4; q++)
                        u[q] = *(const uint2*)(g_h1h + (size_t)s[q] * F1 + sl * 4);
                    acc_pair(acc, u[0], u[1]);
                    acc_pair(acc, u[2], u[3]);
                    e += 4;
                }
                for (; e < re; e++)
                    acc_one(acc, *(const uint2*)(g_h1h + (size_t)g_esrc[e] * F1 + sl * 4));

                float4 z;
                z.x = fmaxf(fmaf(drow, acc.x, b1v.x), 0.0f);
                z.y = fmaxf(fmaf(drow, acc.y, b1v.y), 0.0f);
                z.z = fmaxf(fmaf(drow, acc.z, b1v.z), 0.0f);
                z.w = fmaxf(fmaf(drow, acc.w, b1v.w), 0.0f);
                *(float4*)&zs[r][sl * 4] = z;
            } else {
                *(float4*)&zs[r][sl * 4] = make_float4(0.f, 0.f, 0.f, 0.f);
            }
        }
    }
    __syncthreads();

    int ng = tid >> 3;
    int cg = tid & 7;
    int r0 = ng * 2;
    int c0 = cg * 4;

    float acc[2][4];
#pragma unroll
    for (int i = 0; i < 2; i++)
#pragma unroll
        for (int j = 0; j < 4; j++) acc[i][j] = 0.0f;

#pragma unroll 4
    for (int k = 0; k < F1; k++) {
        float4 wv = *(const float4*)&ws2t[k][c0];
        float z0 = zs[r0 + 0][k];
        float z1 = zs[r0 + 1][k];
        acc[0][0] += z0 * wv.x; acc[0][1] += z0 * wv.y; acc[0][2] += z0 * wv.z; acc[0][3] += z0 * wv.w;
        acc[1][0] += z1 * wv.x; acc[1][1] += z1 * wv.y; acc[1][2] += z1 * wv.z; acc[1][3] += z1 * wv.w;
    }

#pragma unroll
    for (int i = 0; i < 2; i++) {
        int node = base + r0 + i;
        if (node < N_NODES) {
            float d = g_dis[node];
            __half2 p0 = __floats2half2_rn(acc[i][0] * d, acc[i][1] * d);
            __half2 p1 = __floats2half2_rn(acc[i][2] * d, acc[i][3] * d);
            uint2 pk;
            pk.x = *(unsigned*)&p0;
            pk.y = *(unsigned*)&p1;
            *(uint2*)(g_h2h + (size_t)node * F2 + c0) = pk;
        }
    }
}

// ---------------- layer-2 gather + bias -> out ----------------
#define A2_BLOCKS 592
__global__ __launch_bounds__(512) void agg2_kernel(const float* __restrict__ b2,
                                                   float* __restrict__ out) {
    int tid = threadIdx.x;
    int w = tid >> 5, lane = tid & 31;
    int grp = lane >> 3, sl = lane & 7;
    int quad0 = blockIdx.x * 16 + w;
    int n_quads = gridDim.x * 16;
    float4 b2v = ((const float4*)b2)[sl];

    for (int p = quad0; p * 4 + grp < N_NODES; p += n_quads) {
        int row = p * 4 + grp;
        float drow = g_dis[row];
        float4 acc = h4_to_f4(((const uint2*)(g_h2h + (size_t)row * F2))[sl]);

        int rs = g_rowstart[row];
        int re = rs + g_deg[row];
        int e = rs;
        for (; e + 16 <= re; e += 16) {
            int s[16]; uint2 u[16];
#pragma unroll
            for (int q = 0; q < 16; q++) s[q] = g_esrc[e + q];
#pragma unroll
            for (int q = 0; q < 16; q++)
                u[q] = ((const uint2*)(g_h2h + (size_t)s[q] * F2))[sl];
#pragma unroll
            for (int q = 0; q < 8; q++)
                acc_pair(acc, u[2 * q], u[2 * q + 1]);
        }
        if (e + 8 <= re) {
            int s[8]; uint2 u[8];
#pragma unroll
            for (int q = 0; q < 8; q++) s[q] = g_esrc[e + q];
#pragma unroll
            for (int q = 0; q < 8; q++)
                u[q] = ((const uint2*)(g_h2h + (size_t)s[q] * F2))[sl];
#pragma unroll
            for (int q = 0; q < 4; q++)
                acc_pair(acc, u[2 * q], u[2 * q + 1]);
            e += 8;
        }
        if (e + 4 <= re) {
            int s[4]; uint2 u[4];
#pragma unroll
            for (int q = 0; q < 4; q++) s[q] = g_esrc[e + q];
#pragma unroll
            for (int q = 0; q < 4; q++)
                u[q] = ((const uint2*)(g_h2h + (size_t)s[q] * F2))[sl];
            acc_pair(acc, u[0], u[1]);
            acc_pair(acc, u[2], u[3]);
            e += 4;
        }
        for (; e < re; e++)
            acc_one(acc, ((const uint2*)(g_h2h + (size_t)g_esrc[e] * F2))[sl]);

        float4 o;
        o.x = fmaf(drow, acc.x, b2v.x);
        o.y = fmaf(drow, acc.y, b2v.y);
        o.z = fmaf(drow, acc.z, b2v.z);
        o.w = fmaf(drow, acc.w, b2v.w);
        ((float4*)(out + (size_t)row * F2))[sl] = o;
    }
}

// ---------------- launch ----------------
extern "C" void kernel_launch(void* const* d_in, const int* in_sizes, int n_in,
                              void* d_out, int out_size) {
    const float* x  = (const float*)d_in[0];
    const void*  ei = d_in[1];
    const float* W1 = (const float*)d_in[2];
    const float* b1 = (const float*)d_in[3];
    const float* W2 = (const float*)d_in[4];
    const float* b2 = (const float*)d_in[5];
    float* out = (float*)d_out;

    cudaStream_t s2;
    cudaStreamCreateWithFlags(&s2, cudaStreamNonBlocking);
    cudaEvent_t evRoot, evScan, evG;
    cudaEventCreateWithFlags(&evRoot, cudaEventDisableTiming);
    cudaEventCreateWithFlags(&evScan, cudaEventDisableTiming);
    cudaEventCreateWithFlags(&evG, cudaEventDisableTiming);

    // fork at t=0: tensor-core gemm1 (unscaled) depends only on x/W1
    cudaEventRecord(evRoot, 0);
    cudaStreamWaitEvent(s2, evRoot, 0);
    gemm1_kernel<<<(N_NODES + 255) / 256, 256, 0, s2>>>(x, W1);

    // main chain: CSR build
    init_kernel<<<(N_NODES + 255) / 256, 256>>>(ei);
    convert_count_kernel<<<(N_EDGES / 4 + 255) / 256, 256>>>(ei);
    scan_kernel<<<N_SCAN_BLK, SCAN_B>>>();
    cudaEventRecord(evScan, 0);

    // side stream: scale h1 by dis (needs gemm1 done + scan done)
    cudaStreamWaitEvent(s2, evScan, 0);
    scale_h1_kernel<<<(N_NODES * 6 + 255) / 256, 256, 0, s2>>>();
    cudaEventRecord(evG, s2);

    csr_scatter_kernel<<<(N_EDGES / 2 + 255) / 256, 256>>>();

    // join, then the two gather stages
    cudaStreamWaitEvent(0, evG, 0);
    agg1_mid_kernel<<<(N_NODES + A1_NODES - 1) / A1_NODES, 256>>>(b1, W2);
    agg2_kernel<<<A2_BLOCKS, 512>>>(b2, out);
}